// round 4
// baseline (speedup 1.0000x reference)
#include <cuda_runtime.h>
#include <cuda_fp16.h>
#include <mma.h>
#include <math.h>

using namespace nvcuda;

#define NN 50000
#define EE 800000
#define TT 3
#define HEADS 4
#define HDIM 32
#define IND 128            // IN_DIM = HEADS*HDIM
#define TN (TT * NN)       // 150000
#define SCAN_CH 1024
#define SCAN_NB ((TN + SCAN_CH - 1) / SCAN_CH)   // 147

// ---------------- static device scratch ----------------
__device__ __half g_h[(size_t)TT * NN * IND];      // 38.4 MB projected features (fp16)
__device__ float g_esrc[(size_t)TN * HEADS];       // per-node src coefficients
__device__ float g_edst[(size_t)TN * HEADS];       // per-node dst coefficients
__device__ int   g_cnt[TN];                        // in-degree histogram (self-clearing)
__device__ int   g_off[TN + 1];                    // CSR offsets
__device__ int   g_cur[TN];                        // scatter cursors
__device__ int   g_srcbuf[(size_t)TT * EE];        // src id per dst-sorted slot
__device__ int   g_bsum[SCAN_NB];                  // scan block sums

// ---------------- GEMM h[t] = x @ W[t] via tf32 wmma, fused coef epilogue ----------------
#define XLD 136
__global__ void gemm_kernel(const float* __restrict__ x, const float* __restrict__ W,
                            const float* __restrict__ a_src, const float* __restrict__ a_dst) {
    __shared__ float pool[64 * XLD + 16 * IND];   // xsh | Wsh ; Csh aliases xsh
    float* xsh = pool;                 // [64][XLD]
    float* Wsh = pool + 64 * XLD;      // [16][128]

    const int t    = blockIdx.y;
    const int row0 = blockIdx.x * 64;
    const int tid  = threadIdx.x;
    const int w    = tid >> 5;
    const int wr   = w >> 1;           // 0..3
    const int wc   = w & 1;            // 0..1
    const float* Wt = W + (size_t)t * IND * IND;

    for (int i = tid; i < 64 * (IND / 4); i += 256) {
        int r = i >> 5, c4 = i & 31;
        int row = row0 + r;
        float4 v = (row < NN)
            ? __ldg(reinterpret_cast<const float4*>(x + (size_t)row * IND) + c4)
            : make_float4(0.f, 0.f, 0.f, 0.f);
        *reinterpret_cast<float4*>(&xsh[r * XLD + c4 * 4]) = v;
    }

    wmma::fragment<wmma::accumulator, 16, 16, 8, float> c[4];
#pragma unroll
    for (int j = 0; j < 4; ++j) wmma::fill_fragment(c[j], 0.f);

    for (int kt = 0; kt < 8; ++kt) {
        for (int i = tid; i < 16 * (IND / 4); i += 256) {
            int k = i >> 5, c4 = i & 31;
            float4 v = __ldg(reinterpret_cast<const float4*>(
                Wt + (size_t)(kt * 16 + k) * IND) + c4);
            *reinterpret_cast<float4*>(&Wsh[k * IND + c4 * 4]) = v;
        }
        __syncthreads();
#pragma unroll
        for (int k8 = 0; k8 < 2; ++k8) {
            wmma::fragment<wmma::matrix_a, 16, 16, 8, wmma::precision::tf32, wmma::row_major> a;
            wmma::load_matrix_sync(a, &xsh[(wr * 16) * XLD + kt * 16 + k8 * 8], XLD);
#pragma unroll
            for (int e = 0; e < a.num_elements; ++e) a.x[e] = wmma::__float_to_tf32(a.x[e]);
#pragma unroll
            for (int j = 0; j < 4; ++j) {
                wmma::fragment<wmma::matrix_b, 16, 16, 8, wmma::precision::tf32, wmma::row_major> b;
                wmma::load_matrix_sync(b, &Wsh[(k8 * 8) * IND + wc * 64 + j * 16], IND);
#pragma unroll
                for (int e = 0; e < b.num_elements; ++e) b.x[e] = wmma::__float_to_tf32(b.x[e]);
                wmma::mma_sync(c[j], a, b, c[j]);
            }
        }
        __syncthreads();
    }

    float* Csh = pool;                 // [64][128], aliases xsh (mma reads done)
#pragma unroll
    for (int j = 0; j < 4; ++j)
        wmma::store_matrix_sync(&Csh[(wr * 16) * IND + wc * 64 + j * 16], c[j], IND,
                                wmma::mem_row_major);
    __syncthreads();

    const int tc = tid & 31;
    const int tr = tid >> 5;
    float4 av = __ldg(reinterpret_cast<const float4*>(a_src + (size_t)t * IND + tc * 4));
    float4 dv = __ldg(reinterpret_cast<const float4*>(a_dst + (size_t)t * IND + tc * 4));
    const int head = tc >> 3;

#pragma unroll
    for (int i = 0; i < 8; ++i) {
        int r = tr * 8 + i;
        int row = row0 + r;
        float4 hv = *reinterpret_cast<float4*>(&Csh[r * IND + tc * 4]);
        if (row < NN) {
            __half2 p0 = __floats2half2_rn(hv.x, hv.y);
            __half2 p1 = __floats2half2_rn(hv.z, hv.w);
            __half2* hp = reinterpret_cast<__half2*>(g_h + ((size_t)t * NN + row) * IND + tc * 4);
            hp[0] = p0; hp[1] = p1;
        }
        float s = hv.x * av.x + hv.y * av.y + hv.z * av.z + hv.w * av.w;
        float d = hv.x * dv.x + hv.y * dv.y + hv.z * dv.z + hv.w * dv.w;
        s += __shfl_xor_sync(0xffffffffu, s, 1);
        d += __shfl_xor_sync(0xffffffffu, d, 1);
        s += __shfl_xor_sync(0xffffffffu, s, 2);
        d += __shfl_xor_sync(0xffffffffu, d, 2);
        s += __shfl_xor_sync(0xffffffffu, s, 4);
        d += __shfl_xor_sync(0xffffffffu, d, 4);
        if ((tc & 7) == 0 && row < NN) {
            g_esrc[((size_t)t * NN + row) * HEADS + head] = s;
            g_edst[((size_t)t * NN + row) * HEADS + head] = d;
        }
    }
}

// ---------------- histogram of dst in-degree (4 edges/thread) ----------------
__global__ void hist_kernel(const int* __restrict__ edges) {
    int e4 = blockIdx.x * blockDim.x + threadIdx.x;    // EE/4 per type
    int t = blockIdx.y;
    if (e4 >= EE / 4) return;
    int4 d = __ldg(reinterpret_cast<const int4*>(edges + (size_t)t * 2 * EE + EE) + e4);
    int base = t * NN;
    atomicAdd(&g_cnt[base + d.x], 1);
    atomicAdd(&g_cnt[base + d.y], 1);
    atomicAdd(&g_cnt[base + d.z], 1);
    atomicAdd(&g_cnt[base + d.w], 1);
}

// ---------------- hierarchical exclusive scan (scan1 self-clears g_cnt) ----------------
__device__ __forceinline__ int warp_incl_scan(int x) {
#pragma unroll
    for (int o = 1; o < 32; o <<= 1) {
        int y = __shfl_up_sync(0xffffffffu, x, o);
        if ((threadIdx.x & 31) >= o) x += y;
    }
    return x;
}

__global__ void scan1_kernel() {
    __shared__ int wsum[32];
    int i = blockIdx.x * SCAN_CH + threadIdx.x;
    int v = 0;
    if (i < TN) { v = g_cnt[i]; g_cnt[i] = 0; }       // read + clear for next replay
    int x = warp_incl_scan(v);
    int wid = threadIdx.x >> 5;
    if ((threadIdx.x & 31) == 31) wsum[wid] = x;
    __syncthreads();
    if (threadIdx.x < 32) {
        int s = wsum[threadIdx.x];
        int xs = warp_incl_scan(s);
        wsum[threadIdx.x] = xs - s;
    }
    __syncthreads();
    int excl = x - v + wsum[wid];
    if (i < TN) g_off[i] = excl;
    if (threadIdx.x == SCAN_CH - 1) g_bsum[blockIdx.x] = excl + v;
}

__global__ void scan2_kernel() {
    __shared__ int wsum[8];
    int tid = threadIdx.x;
    int v = (tid < SCAN_NB) ? g_bsum[tid] : 0;
    int x = warp_incl_scan(v);
    int wid = tid >> 5;
    if ((tid & 31) == 31) wsum[wid] = x;
    __syncthreads();
    if (tid < 8) {
        int s = wsum[tid];
        int xs = s;
#pragma unroll
        for (int o = 1; o < 8; o <<= 1) {
            int y = __shfl_up_sync(0x000000ffu, xs, o);
            if (tid >= o) xs += y;
        }
        wsum[tid] = xs - s;
    }
    __syncthreads();
    if (tid < SCAN_NB) g_bsum[tid] = x - v + wsum[wid];
}

__global__ void scan3_kernel() {
    int i = blockIdx.x * blockDim.x + threadIdx.x;
    if (i < TN) {
        int o = g_off[i] + g_bsum[i >> 10];
        g_off[i] = o;
        g_cur[i] = o;
    }
    if (i == 0) g_off[TN] = TT * EE;
}

// ---------------- scatter src ids into dst-sorted order (4 edges/thread) ----------------
__global__ void scatter_kernel(const int* __restrict__ edges) {
    int e4 = blockIdx.x * blockDim.x + threadIdx.x;
    int t = blockIdx.y;
    if (e4 >= EE / 4) return;
    const int* eb = edges + (size_t)t * 2 * EE;
    int4 s = __ldg(reinterpret_cast<const int4*>(eb) + e4);
    int4 d = __ldg(reinterpret_cast<const int4*>(eb + EE) + e4);
    int base = t * NN;
    int p0 = atomicAdd(&g_cur[base + d.x], 1);
    int p1 = atomicAdd(&g_cur[base + d.y], 1);
    int p2 = atomicAdd(&g_cur[base + d.z], 1);
    int p3 = atomicAdd(&g_cur[base + d.w], 1);
    g_srcbuf[p0] = s.x;
    g_srcbuf[p1] = s.y;
    g_srcbuf[p2] = s.z;
    g_srcbuf[p3] = s.w;
}

// ---------------- gather: 4-wide pipelined softmax aggregation + ELU ----------------
__global__ void gather_kernel(float* __restrict__ out) {
    int i = (blockIdx.x * blockDim.x + threadIdx.x) >> 5;   // node in [0, TN)
    int lane = threadIdx.x & 31;
    if (i >= TN) return;
    const int head = lane >> 3;
    const size_t tbase = (size_t)(i / NN) * NN;

    int beg = __ldg(&g_off[i]);
    int end = __ldg(&g_off[i + 1]);

    float edh = __ldg(&g_edst[(size_t)i * HEADS + head]);
    const uint2* h2 = reinterpret_cast<const uint2*>(g_h);

    float4 acc = make_float4(0.f, 0.f, 0.f, 0.f);
    float dsum = 0.f;

    for (int j = beg; j < end; j += 4) {
        int n = end - j;
        // clamp invalid slots to s0; mask their contribution with w=0
        int s0 = __ldg(&g_srcbuf[j]);
        int s1 = (n > 1) ? __ldg(&g_srcbuf[j + 1]) : s0;
        int s2 = (n > 2) ? __ldg(&g_srcbuf[j + 2]) : s0;
        int s3 = (n > 3) ? __ldg(&g_srcbuf[j + 3]) : s0;
        float w1 = (n > 1) ? 1.f : 0.f;
        float w2 = (n > 2) ? 1.f : 0.f;
        float w3 = (n > 3) ? 1.f : 0.f;

        size_t b0 = tbase + s0, b1 = tbase + s1, b2 = tbase + s2, b3 = tbase + s3;
        // issue all loads up front (8 independent requests in flight)
        float ev0 = __ldg(&g_esrc[b0 * HEADS + head]);
        float ev1 = __ldg(&g_esrc[b1 * HEADS + head]);
        float ev2 = __ldg(&g_esrc[b2 * HEADS + head]);
        float ev3 = __ldg(&g_esrc[b3 * HEADS + head]);
        uint2 r0 = __ldg(h2 + b0 * (IND / 4) + lane);
        uint2 r1 = __ldg(h2 + b1 * (IND / 4) + lane);
        uint2 r2 = __ldg(h2 + b2 * (IND / 4) + lane);
        uint2 r3 = __ldg(h2 + b3 * (IND / 4) + lane);

        float v0 = ev0 + edh; v0 = (v0 > 0.f) ? v0 : 0.2f * v0;
        float v1 = ev1 + edh; v1 = (v1 > 0.f) ? v1 : 0.2f * v1;
        float v2 = ev2 + edh; v2 = (v2 > 0.f) ? v2 : 0.2f * v2;
        float v3 = ev3 + edh; v3 = (v3 > 0.f) ? v3 : 0.2f * v3;
        float p0 = __expf(v0);
        float p1 = __expf(v1) * w1;
        float p2 = __expf(v2) * w2;
        float p3 = __expf(v3) * w3;
        dsum += p0 + p1 + p2 + p3;

        float2 a0 = __half22float2(*reinterpret_cast<__half2*>(&r0.x));
        float2 c0 = __half22float2(*reinterpret_cast<__half2*>(&r0.y));
        float2 a1 = __half22float2(*reinterpret_cast<__half2*>(&r1.x));
        float2 c1 = __half22float2(*reinterpret_cast<__half2*>(&r1.y));
        float2 a2 = __half22float2(*reinterpret_cast<__half2*>(&r2.x));
        float2 c2 = __half22float2(*reinterpret_cast<__half2*>(&r2.y));
        float2 a3 = __half22float2(*reinterpret_cast<__half2*>(&r3.x));
        float2 c3 = __half22float2(*reinterpret_cast<__half2*>(&r3.y));

        acc.x += a0.x * p0 + a1.x * p1 + a2.x * p2 + a3.x * p3;
        acc.y += a0.y * p0 + a1.y * p1 + a2.y * p2 + a3.y * p3;
        acc.z += c0.x * p0 + c1.x * p1 + c2.x * p2 + c3.x * p3;
        acc.w += c0.y * p0 + c1.y * p1 + c2.y * p2 + c3.y * p3;
    }

    float inv = 1.f / (dsum + 1e-9f);
    acc.x *= inv; acc.y *= inv; acc.z *= inv; acc.w *= inv;
    acc.x = (acc.x > 0.f) ? acc.x : expm1f(acc.x);
    acc.y = (acc.y > 0.f) ? acc.y : expm1f(acc.y);
    acc.z = (acc.z > 0.f) ? acc.z : expm1f(acc.z);
    acc.w = (acc.w > 0.f) ? acc.w : expm1f(acc.w);

    const size_t total4 = (size_t)TN * (IND / 4);
    float4* o4 = reinterpret_cast<float4*>(out);
    o4[(size_t)i * (IND / 4) + lane] = acc;             // gat
    o4[total4 + (size_t)i * (IND / 4) + lane] = acc;    // gcn (identical branch)
}

// ---------------- launch ----------------
extern "C" void kernel_launch(void* const* d_in, const int* in_sizes, int n_in,
                              void* d_out, int out_size) {
    const float* embedding = (const float*)d_in[0];   // [N,128]
    const int*   edges     = (const int*)d_in[1];     // [3,2,E]
    const float* W         = (const float*)d_in[2];   // [3,128,4,32]
    const float* a_src     = (const float*)d_in[3];   // [3,4,32]
    const float* a_dst     = (const float*)d_in[4];   // [3,4,32]
    float* out = (float*)d_out;                       // [2,3,N,128]
    (void)in_sizes; (void)n_in; (void)out_size;

    {
        dim3 grid((NN + 63) / 64, TT);
        gemm_kernel<<<grid, 256>>>(embedding, W, a_src, a_dst);
    }
    {
        dim3 grid((EE / 4 + 255) / 256, TT);
        hist_kernel<<<grid, 256>>>(edges);
    }
    scan1_kernel<<<SCAN_NB, SCAN_CH>>>();
    scan2_kernel<<<1, 256>>>();
    scan3_kernel<<<(TN + 255) / 256, 256>>>();
    {
        dim3 grid((EE / 4 + 255) / 256, TT);
        scatter_kernel<<<grid, 256>>>(edges);
    }
    {
        int blocks = (TN * 32 + 255) / 256;
        gather_kernel<<<blocks, 256>>>(out);
    }
}